// round 2
// baseline (speedup 1.0000x reference)
#include <cuda_runtime.h>
#include <math.h>

#define BB 16
#define NN 325
#define DD 64
#define HH 4
#define DHH 16
#define STEPS 12
#define MAXDEG 128
#define CLX 8
#define TPB 384
#define NWARP (TPB/32)
#define RPC 41          // rows per CTA: ranks 0-6 -> 41, rank 7 -> 38
#define QSLOT 4         // max rows per warp in attention map

// ---------------- global scratch (static: no allocations) ----------------
__device__ float g_x [BB*NN*DD];
__device__ float g_h [2][BB*NN*DD];
__device__ float g_es[2][BB*HH*NN];
__device__ float g_ed[2][BB*HH*NN];
__device__ float g_W1t[DD*DD];          // W1 transposed: [c*64 + k]
__device__ int   g_adj_cnt[NN];
__device__ int   g_adj_idx[NN*MAXDEG];

// ---------------- prep: adjacency CSR (ordered) + W1 transpose -----------
__global__ void prep_kernel(const float* __restrict__ graph,
                            const float* __restrict__ W1)
{
    int gt = blockIdx.x * blockDim.x + threadIdx.x;
    for (int i = gt; i < DD*DD; i += gridDim.x * blockDim.x)
        g_W1t[(i & 63) * DD + (i >> 6)] = W1[i];

    int gwarp = gt >> 5;
    int lane  = threadIdx.x & 31;
    if (gwarp >= NN) return;
    const int i = gwarp;
    const float* row = graph + (size_t)i * NN;
    int c = 0;
    for (int j0 = 0; j0 < NN; j0 += 32) {
        int j = j0 + lane;
        bool v = (j < NN) && (row[j] > 0.9f || j == i);
        unsigned m = __ballot_sync(0xffffffffu, v);
        if (v) {
            int pos = c + __popc(m & ((1u << lane) - 1u));
            if (pos < MAXDEG) g_adj_idx[i * MAXDEG + pos] = j;
        }
        c += __popc(m);
    }
    if (lane == 0) g_adj_cnt[i] = (c > MAXDEG) ? MAXDEG : c;
}

// ---------------- cluster barrier + gpu-scope fences ----------------------
__device__ __forceinline__ void cluster_sync_fenced()
{
    __threadfence();   // release: order STG before peers' reads
    asm volatile("barrier.cluster.arrive.aligned;" ::: "memory");
    asm volatile("barrier.cluster.wait.aligned;"   ::: "memory");
    __threadfence();   // acquire: CCTL.IVALL -> no stale L1 hits on g_h/g_es/g_ed
}

__device__ __forceinline__ float f4c(const float4& v, int kk)
{
    return (kk == 0) ? v.x : (kk == 1) ? v.y : (kk == 2) ? v.z : v.w;
}

// ---------------- readout: out = tanh(row@W1 + b1) @ W2 + b2 -------------
__device__ __forceinline__ void warp_readout(
    const float* __restrict__ rb, const float* __restrict__ sB1,
    const float* __restrict__ sW2v, float bias2,
    float* __restrict__ outp, int lane)
{
    const float4* W1t4 = reinterpret_cast<const float4*>(g_W1t);
    float s0 = sB1[lane], s1 = sB1[lane + 32];
    #pragma unroll
    for (int k4 = 0; k4 < 16; ++k4) {
        float4 yv = reinterpret_cast<const float4*>(rb)[k4];
        float4 w0 = W1t4[lane * 16 + k4];
        float4 w1 = W1t4[(lane + 32) * 16 + k4];
        s0 += yv.x*w0.x + yv.y*w0.y + yv.z*w0.z + yv.w*w0.w;
        s1 += yv.x*w1.x + yv.y*w1.y + yv.z*w1.z + yv.w*w1.w;
    }
    float t = tanhf(s0) * sW2v[lane] + tanhf(s1) * sW2v[lane + 32];
    #pragma unroll
    for (int off = 16; off; off >>= 1)
        t += __shfl_xor_sync(0xffffffffu, t, off);
    if (lane == 0) *outp = t + bias2;
}

// ---------------- main: one 8-CTA cluster per batch -----------------------
__global__ void __launch_bounds__(TPB, 1) __cluster_dims__(CLX, 1, 1)
ode_kernel(const float* __restrict__ y0,
           const float* __restrict__ Wg,
           const float* __restrict__ a_src,
           const float* __restrict__ a_dst,
           const float* __restrict__ b1,
           const float* __restrict__ W2,
           const float* __restrict__ b2,
           float* __restrict__ out)
{
    __shared__ float sW[2*DD*DD];          // 32 KB
    __shared__ float sAS[2*DD], sAD[2*DD];
    __shared__ float sW2v[DD], sB1[DD];
    __shared__ float sAlpha[NWARP*MAXDEG]; // 6 KB
    __shared__ float sRow[NWARP*DD];       // 3 KB

    const int b    = blockIdx.x / CLX;
    const int rank = blockIdx.x % CLX;
    const int tid  = threadIdx.x;
    const int wid  = tid >> 5;
    const int lane = tid & 31;
    const int base  = rank * RPC;
    const int nrows = (rank == CLX - 1) ? (NN - base) : RPC;

    for (int i = tid; i < 2*DD*DD; i += TPB) sW[i] = Wg[i];
    for (int i = tid; i < 2*DD;    i += TPB) { sAS[i] = a_src[i]; sAD[i] = a_dst[i]; }
    for (int i = tid; i < DD;      i += TPB) { sW2v[i] = W2[i]; sB1[i] = b1[i]; }
    __syncthreads();
    const float bias2 = b2[0];

    float* rb = sRow + wid * DD;
    const size_t bo = (size_t)b * NN * DD;

    // RK4 state in registers: rows wid, wid+12, wid+24, wid+36 of this CTA
    float yR[QSLOT][2], accR[QSLOT][2];

    // ---- init y + t=0 readout ----
    for (int q = 0, r = wid; r < nrows; ++q, r += NWARP) {
        const size_t ro = bo + (size_t)(base + r) * DD;
        yR[q][0] = y0[ro + lane];
        yR[q][1] = y0[ro + lane + 32];
        g_x[ro + lane]      = yR[q][0];
        g_x[ro + lane + 32] = yR[q][1];
        rb[lane]      = yR[q][0];
        rb[lane + 32] = yR[q][1];
        __syncwarp();
        warp_readout(rb, sB1, sW2v, bias2,
                     out + ((size_t)(b*(STEPS+1) + 0))*NN + base + r, lane);
        __syncwarp();
    }
    __syncthreads();

    for (int s = 0; s < STEPS; ++s) {
        const float dt = (float)(s+1)*0.1f - (float)s*0.1f;
        for (int st = 0; st < 4; ++st) {
            for (int l = 0; l < 2; ++l) {
                __syncthreads();
                // ======= Phase A: h = x@W, e_src, e_dst (rows wid*4..+3) ==
                {
                    const float* Wl = sW + l*DD*DD;
                    const int r0 = wid * 4;
                    if (r0 < nrows) {
                        int ri[4];
                        #pragma unroll
                        for (int r = 0; r < 4; ++r) {
                            int rr = r0 + r; if (rr > nrows-1) rr = nrows-1;
                            ri[r] = base + rr;
                        }
                        float a00=0,a01=0,a10=0,a11=0,a20=0,a21=0,a30=0,a31=0;
                        const float* xp = g_x + bo;
                        #pragma unroll 2
                        for (int k = 0; k < DD; k += 4) {
                            float4 x0 = *reinterpret_cast<const float4*>(xp + (size_t)ri[0]*DD + k);
                            float4 x1 = *reinterpret_cast<const float4*>(xp + (size_t)ri[1]*DD + k);
                            float4 x2 = *reinterpret_cast<const float4*>(xp + (size_t)ri[2]*DD + k);
                            float4 x3 = *reinterpret_cast<const float4*>(xp + (size_t)ri[3]*DD + k);
                            #pragma unroll
                            for (int kk = 0; kk < 4; ++kk) {
                                float w0 = Wl[(k+kk)*DD + lane];
                                float w1 = Wl[(k+kk)*DD + lane + 32];
                                float c0 = f4c(x0,kk), c1 = f4c(x1,kk);
                                float c2 = f4c(x2,kk), c3 = f4c(x3,kk);
                                a00 += c0*w0; a01 += c0*w1;
                                a10 += c1*w0; a11 += c1*w1;
                                a20 += c2*w0; a21 += c2*w1;
                                a30 += c3*w0; a31 += c3*w1;
                            }
                        }
                        float accs[4][2] = {{a00,a01},{a10,a11},{a20,a21},{a30,a31}};
                        #pragma unroll
                        for (int r = 0; r < 4; ++r) {
                            if (r0 + r >= nrows) break;
                            const int row = base + r0 + r;
                            float* hp = g_h[l] + bo + (size_t)row*DD;
                            hp[lane]      = accs[r][0];
                            hp[lane + 32] = accs[r][1];
                            float v1 = accs[r][0]*sAS[l*DD+lane];
                            float v2 = accs[r][1]*sAS[l*DD+lane+32];
                            float v3 = accs[r][0]*sAD[l*DD+lane];
                            float v4 = accs[r][1]*sAD[l*DD+lane+32];
                            #pragma unroll
                            for (int off = 8; off; off >>= 1) {
                                v1 += __shfl_down_sync(0xffffffffu, v1, off, 16);
                                v2 += __shfl_down_sync(0xffffffffu, v2, off, 16);
                                v3 += __shfl_down_sync(0xffffffffu, v3, off, 16);
                                v4 += __shfl_down_sync(0xffffffffu, v4, off, 16);
                            }
                            if ((lane & 15) == 0) {
                                const int h0 = lane >> 4;   // 0 or 1
                                g_es[l][(b*HH + h0    )*NN + row] = v1;
                                g_es[l][(b*HH + h0 + 2)*NN + row] = v2;
                                g_ed[l][(b*HH + h0    )*NN + row] = v3;
                                g_ed[l][(b*HH + h0 + 2)*NN + row] = v4;
                            }
                        }
                    }
                }
                __syncthreads();
                cluster_sync_fenced();
                // ======= Phase B: sparse attention + fused epilogue =======
                {
                    const float* esl = g_es[l] + b*HH*NN;
                    const float* edl = g_ed[l] + b*HH*NN;
                    const float* hl  = g_h[l] + bo;
                    float* alpha = sAlpha + wid * MAXDEG;
                    const int sub = lane >> 4, dh = lane & 15;
                    for (int q = 0, r = wid; r < nrows; ++q, r += NWARP) {
                        const int row = base + r;
                        const int cnt = g_adj_cnt[row];
                        const int* idx = g_adj_idx + row * MAXDEG;
                        #pragma unroll 1
                        for (int hd = 0; hd < HH; ++hd) {
                            const float es = esl[hd*NN + row];
                            float m = -3.0e38f;
                            for (int j0 = lane; j0 < cnt; j0 += 32) {
                                float e = es + edl[hd*NN + idx[j0]];
                                e = (e > 0.f) ? e : 0.2f * e;      // leaky_relu
                                alpha[j0] = e;
                                m = fmaxf(m, e);
                            }
                            #pragma unroll
                            for (int off = 16; off; off >>= 1)
                                m = fmaxf(m, __shfl_xor_sync(0xffffffffu, m, off));
                            float ssum = 0.f;
                            __syncwarp();
                            for (int j0 = lane; j0 < cnt; j0 += 32) {
                                float p = __expf(alpha[j0] - m);
                                alpha[j0] = p;
                                ssum += p;
                            }
                            #pragma unroll
                            for (int off = 16; off; off >>= 1)
                                ssum += __shfl_xor_sync(0xffffffffu, ssum, off);
                            __syncwarp();
                            float a = 0.f;
                            for (int j0 = sub; j0 < cnt; j0 += 2)
                                a += alpha[j0] * hl[(size_t)idx[j0]*DD + hd*DHH + dh];
                            a += __shfl_xor_sync(0xffffffffu, a, 16);
                            if (sub == 0) rb[hd*DHH + dh] = a / ssum;
                            __syncwarp();
                        }
                        // ---- fused epilogue (row-local, warp-local) ----
                        const size_t ro = bo + (size_t)row * DD;
                        float k0 = rb[lane], k1 = rb[lane + 32];
                        if (l == 0) {       // ELU between layers
                            g_x[ro + lane]      = (k0 > 0.f) ? k0 : (__expf(k0) - 1.f);
                            g_x[ro + lane + 32] = (k1 > 0.f) ? k1 : (__expf(k1) - 1.f);
                        } else {            // RK4 bookkeeping
                            if (st == 0) { accR[q][0] = k0; accR[q][1] = k1; }
                            else {
                                float w = (st == 3) ? 1.f : 2.f;
                                accR[q][0] += w * k0; accR[q][1] += w * k1;
                            }
                            if (st < 3) {
                                float cc = (st == 2) ? dt : 0.5f * dt;
                                g_x[ro + lane]      = yR[q][0] + cc * k0;
                                g_x[ro + lane + 32] = yR[q][1] + cc * k1;
                            } else {
                                yR[q][0] += dt * (1.f/6.f) * accR[q][0];
                                yR[q][1] += dt * (1.f/6.f) * accR[q][1];
                                g_x[ro + lane]      = yR[q][0];
                                g_x[ro + lane + 32] = yR[q][1];
                            }
                        }
                    }
                }
            } // l
        } // st
        // ---- readout for t = s+1 (warp-local, from register y) ----
        for (int q = 0, r = wid; r < nrows; ++q, r += NWARP) {
            rb[lane]      = yR[q][0];
            rb[lane + 32] = yR[q][1];
            __syncwarp();
            warp_readout(rb, sB1, sW2v, bias2,
                         out + ((size_t)(b*(STEPS+1) + s + 1))*NN + base + r, lane);
            __syncwarp();
        }
    } // s
}

extern "C" void kernel_launch(void* const* d_in, const int* in_sizes, int n_in,
                              void* d_out, int out_size)
{
    const float* y0    = (const float*)d_in[0];
    const float* graph = (const float*)d_in[1];
    const float* Wg    = (const float*)d_in[2];
    const float* a_src = (const float*)d_in[3];
    const float* a_dst = (const float*)d_in[4];
    const float* W1    = (const float*)d_in[5];
    const float* b1    = (const float*)d_in[6];
    const float* W2    = (const float*)d_in[7];
    const float* b2    = (const float*)d_in[8];
    float* out = (float*)d_out;

    prep_kernel<<<41, 256>>>(graph, W1);
    ode_kernel<<<BB*CLX, TPB>>>(y0, Wg, a_src, a_dst, b1, W2, b2, out);
}

// round 3
// speedup vs baseline: 1.6908x; 1.6908x over previous
#include <cuda_runtime.h>
#include <math.h>

#define BB 16
#define NN 325
#define DD 64
#define HH 4
#define STEPS 12
#define MAXD 128
#define CLX 8
#define TPB 384
#define NWARP (TPB/32)
#define RPC 41          // rows per CTA: ranks 0-6 -> 41, rank 7 -> 38
#define QSLOT 4

// ---- dynamic smem layout (float offsets) ----
#define OFF_W     0        // 2*64*64      = 8192
#define OFF_X     8192     // 41*64        = 2624
#define OFF_ALPHA 10816    // 12*128*4     = 6144
#define OFF_ROW   16960    // 12*64        = 768
#define OFF_ES    17728    // 41*4 pad     = 176
#define OFF_AS    17904    // 128
#define OFF_AD    18032    // 128
#define OFF_W2    18160    // 64
#define OFF_B1    18224    // 64
#define OFF_CNT   18288    // 48 (ints)
#define OFF_IDX   18336    // 41*128 ints  = 5248
#define SMEM_FLOATS 23584
#define SMEM_BYTES (SMEM_FLOATS*4)   // 94336

// ---------------- global scratch (static: no allocations) ----------------
__device__ float g_h  [2][BB*NN*DD];
__device__ float g_ed4[2][BB*NN*HH];    // interleaved: [node*4 + head]
__device__ float g_W1t[DD*DD];          // W1 transposed: [c*64 + k]
__device__ int   g_adj_cnt[NN];
__device__ int   g_adj_idx[NN*MAXD];

// ---------------- prep: adjacency CSR (ordered) + W1 transpose -----------
__global__ void prep_kernel(const float* __restrict__ graph,
                            const float* __restrict__ W1)
{
    int gt = blockIdx.x * blockDim.x + threadIdx.x;
    for (int i = gt; i < DD*DD; i += gridDim.x * blockDim.x)
        g_W1t[(i & 63) * DD + (i >> 6)] = W1[i];

    int gwarp = gt >> 5;
    int lane  = threadIdx.x & 31;
    if (gwarp >= NN) return;
    const int i = gwarp;
    const float* row = graph + (size_t)i * NN;
    int c = 0;
    for (int j0 = 0; j0 < NN; j0 += 32) {
        int j = j0 + lane;
        bool v = (j < NN) && (row[j] > 0.9f || j == i);
        unsigned m = __ballot_sync(0xffffffffu, v);
        if (v) {
            int pos = c + __popc(m & ((1u << lane) - 1u));
            if (pos < MAXD) g_adj_idx[i * MAXD + pos] = j;
        }
        c += __popc(m);
    }
    if (lane == 0) g_adj_cnt[i] = (c > MAXD) ? MAXD : c;
}

__device__ __forceinline__ void cluster_sync_rel()
{
    __threadfence();   // release: drain STG before peers read (L2 path)
    asm volatile("barrier.cluster.arrive.aligned;" ::: "memory");
    asm volatile("barrier.cluster.wait.aligned;"   ::: "memory");
}

__device__ __forceinline__ float f4c(const float4& v, int kk)
{
    return (kk == 0) ? v.x : (kk == 1) ? v.y : (kk == 2) ? v.z : v.w;
}

// ---------------- readout: out = tanh(row@W1 + b1) @ W2 + b2 -------------
__device__ __forceinline__ void warp_readout(
    const float* __restrict__ rb, const float* __restrict__ sB1,
    const float* __restrict__ sW2v, float bias2,
    float* __restrict__ outp, int lane)
{
    const float4* W1t4 = reinterpret_cast<const float4*>(g_W1t);
    float s0 = sB1[lane], s1 = sB1[lane + 32];
    #pragma unroll
    for (int k4 = 0; k4 < 16; ++k4) {
        float4 yv = reinterpret_cast<const float4*>(rb)[k4];
        float4 w0 = W1t4[lane * 16 + k4];
        float4 w1 = W1t4[(lane + 32) * 16 + k4];
        s0 += yv.x*w0.x + yv.y*w0.y + yv.z*w0.z + yv.w*w0.w;
        s1 += yv.x*w1.x + yv.y*w1.y + yv.z*w1.z + yv.w*w1.w;
    }
    float t = tanhf(s0) * sW2v[lane] + tanhf(s1) * sW2v[lane + 32];
    #pragma unroll
    for (int off = 16; off; off >>= 1)
        t += __shfl_xor_sync(0xffffffffu, t, off);
    if (lane == 0) *outp = t + bias2;
}

// ---------------- main: one 8-CTA cluster per batch -----------------------
__global__ void __launch_bounds__(TPB, 1) __cluster_dims__(CLX, 1, 1)
ode_kernel(const float* __restrict__ y0,
           const float* __restrict__ Wg,
           const float* __restrict__ a_src,
           const float* __restrict__ a_dst,
           const float* __restrict__ b1,
           const float* __restrict__ W2,
           const float* __restrict__ b2,
           float* __restrict__ out)
{
    extern __shared__ float sm[];
    float* sW   = sm + OFF_W;
    float* sX   = sm + OFF_X;
    float* sAl  = sm + OFF_ALPHA;
    float* sRow = sm + OFF_ROW;
    float* sEs  = sm + OFF_ES;
    float* sAS  = sm + OFF_AS;
    float* sAD  = sm + OFF_AD;
    float* sW2v = sm + OFF_W2;
    float* sB1  = sm + OFF_B1;
    int*   sCnt = (int*)(sm + OFF_CNT);
    int*   sIdx = (int*)(sm + OFF_IDX);

    const int b    = blockIdx.x / CLX;
    const int rank = blockIdx.x % CLX;
    const int tid  = threadIdx.x;
    const int wid  = tid >> 5;
    const int lane = tid & 31;
    const int base  = rank * RPC;
    const int nrows = (rank == CLX - 1) ? (NN - base) : RPC;

    for (int i = tid; i < 2*DD*DD; i += TPB) sW[i] = Wg[i];
    for (int i = tid; i < 2*DD;    i += TPB) { sAS[i] = a_src[i]; sAD[i] = a_dst[i]; }
    for (int i = tid; i < DD;      i += TPB) { sW2v[i] = W2[i]; sB1[i] = b1[i]; }
    for (int i = tid; i < nrows;   i += TPB) sCnt[i] = g_adj_cnt[base + i];
    for (int i = tid; i < nrows*MAXD; i += TPB)
        sIdx[i] = g_adj_idx[base*MAXD + i];
    const float bias2 = b2[0];

    float* rb = sRow + wid * DD;
    const size_t bo = (size_t)b * NN * DD;

    float yR[QSLOT][2], accR[QSLOT][2];

    __syncthreads();
    // ---- init y/x + t=0 readout ----
    for (int q = 0, r = wid; r < nrows; ++q, r += NWARP) {
        const size_t ro = bo + (size_t)(base + r) * DD;
        yR[q][0] = y0[ro + lane];
        yR[q][1] = y0[ro + lane + 32];
        sX[r*DD + lane]      = yR[q][0];
        sX[r*DD + lane + 32] = yR[q][1];
        rb[lane]      = yR[q][0];
        rb[lane + 32] = yR[q][1];
        __syncwarp();
        warp_readout(rb, sB1, sW2v, bias2,
                     out + ((size_t)(b*(STEPS+1) + 0))*NN + base + r, lane);
        __syncwarp();
    }

    for (int s = 0; s < STEPS; ++s) {
        const float dt = (float)(s+1)*0.1f - (float)s*0.1f;
        for (int st = 0; st < 4; ++st) {
            for (int l = 0; l < 2; ++l) {
                __syncthreads();
                // ======= Phase A: h = x@W, e_src, e_dst (all-smem GEMM) ===
                {
                    const float* Wl = sW + l*DD*DD;
                    const int r0 = wid * 4;
                    if (r0 < nrows) {
                        int rl[4];
                        #pragma unroll
                        for (int r = 0; r < 4; ++r) {
                            int rr = r0 + r; if (rr > nrows-1) rr = nrows-1;
                            rl[r] = rr;
                        }
                        float a00=0,a01=0,a10=0,a11=0,a20=0,a21=0,a30=0,a31=0;
                        const float4* x4 = reinterpret_cast<const float4*>(sX);
                        #pragma unroll 2
                        for (int k = 0; k < DD; k += 4) {
                            float4 x0 = x4[rl[0]*16 + (k>>2)];
                            float4 x1 = x4[rl[1]*16 + (k>>2)];
                            float4 x2 = x4[rl[2]*16 + (k>>2)];
                            float4 x3 = x4[rl[3]*16 + (k>>2)];
                            #pragma unroll
                            for (int kk = 0; kk < 4; ++kk) {
                                float w0 = Wl[(k+kk)*DD + lane];
                                float w1 = Wl[(k+kk)*DD + lane + 32];
                                float c0 = f4c(x0,kk), c1 = f4c(x1,kk);
                                float c2 = f4c(x2,kk), c3 = f4c(x3,kk);
                                a00 += c0*w0; a01 += c0*w1;
                                a10 += c1*w0; a11 += c1*w1;
                                a20 += c2*w0; a21 += c2*w1;
                                a30 += c3*w0; a31 += c3*w1;
                            }
                        }
                        float accs[4][2] = {{a00,a01},{a10,a11},{a20,a21},{a30,a31}};
                        #pragma unroll
                        for (int r = 0; r < 4; ++r) {
                            if (r0 + r >= nrows) break;
                            const int row = base + r0 + r;
                            float* hp = g_h[l] + bo + (size_t)row*DD;
                            __stcg(hp + lane,      accs[r][0]);
                            __stcg(hp + lane + 32, accs[r][1]);
                            float v1 = accs[r][0]*sAS[l*DD+lane];
                            float v2 = accs[r][1]*sAS[l*DD+lane+32];
                            float v3 = accs[r][0]*sAD[l*DD+lane];
                            float v4 = accs[r][1]*sAD[l*DD+lane+32];
                            #pragma unroll
                            for (int off = 8; off; off >>= 1) {
                                v1 += __shfl_down_sync(0xffffffffu, v1, off, 16);
                                v2 += __shfl_down_sync(0xffffffffu, v2, off, 16);
                                v3 += __shfl_down_sync(0xffffffffu, v3, off, 16);
                                v4 += __shfl_down_sync(0xffffffffu, v4, off, 16);
                            }
                            if ((lane & 15) == 0) {
                                const int h0 = lane >> 4;   // 0 or 1
                                sEs[(r0 + r)*4 + h0]     = v1;
                                sEs[(r0 + r)*4 + h0 + 2] = v2;
                                float* ed = g_ed4[l] + ((size_t)b*NN + row)*4;
                                __stcg(ed + h0,     v3);
                                __stcg(ed + h0 + 2, v4);
                            }
                        }
                    }
                }
                __syncthreads();
                cluster_sync_rel();
                // ======= Phase B: sparse attention (all heads fused) ======
                {
                    const float* hl  = g_h[l] + bo;
                    const float* edb = g_ed4[l] + (size_t)b*NN*4;
                    float4* aw = reinterpret_cast<float4*>(sAl) + wid * MAXD;
                    const float* awf = sAl + wid * MAXD * 4;
                    const int hsel = lane >> 4;
                    for (int q = 0, r = wid; r < nrows; ++q, r += NWARP) {
                        const int row = base + r;
                        const int cnt = sCnt[r];
                        const int* idxr = sIdx + r * MAXD;
                        float4 esv = reinterpret_cast<const float4*>(sEs)[r];
                        float m0=-3e38f, m1=-3e38f, m2=-3e38f, m3=-3e38f;
                        for (int j0 = lane; j0 < cnt; j0 += 32) {
                            int j = idxr[j0];
                            float4 ev = __ldcg(reinterpret_cast<const float4*>(edb + j*4));
                            float e0 = esv.x + ev.x; e0 = (e0 > 0.f) ? e0 : 0.2f*e0;
                            float e1 = esv.y + ev.y; e1 = (e1 > 0.f) ? e1 : 0.2f*e1;
                            float e2 = esv.z + ev.z; e2 = (e2 > 0.f) ? e2 : 0.2f*e2;
                            float e3 = esv.w + ev.w; e3 = (e3 > 0.f) ? e3 : 0.2f*e3;
                            aw[j0] = make_float4(e0, e1, e2, e3);
                            m0 = fmaxf(m0, e0); m1 = fmaxf(m1, e1);
                            m2 = fmaxf(m2, e2); m3 = fmaxf(m3, e3);
                        }
                        #pragma unroll
                        for (int off = 16; off; off >>= 1) {
                            m0 = fmaxf(m0, __shfl_xor_sync(0xffffffffu, m0, off));
                            m1 = fmaxf(m1, __shfl_xor_sync(0xffffffffu, m1, off));
                            m2 = fmaxf(m2, __shfl_xor_sync(0xffffffffu, m2, off));
                            m3 = fmaxf(m3, __shfl_xor_sync(0xffffffffu, m3, off));
                        }
                        float s0=0.f, s1=0.f, s2=0.f, s3=0.f;
                        for (int j0 = lane; j0 < cnt; j0 += 32) {
                            float4 v = aw[j0];
                            v.x = __expf(v.x - m0); v.y = __expf(v.y - m1);
                            v.z = __expf(v.z - m2); v.w = __expf(v.w - m3);
                            aw[j0] = v;
                            s0 += v.x; s1 += v.y; s2 += v.z; s3 += v.w;
                        }
                        #pragma unroll
                        for (int off = 16; off; off >>= 1) {
                            s0 += __shfl_xor_sync(0xffffffffu, s0, off);
                            s1 += __shfl_xor_sync(0xffffffffu, s1, off);
                            s2 += __shfl_xor_sync(0xffffffffu, s2, off);
                            s3 += __shfl_xor_sync(0xffffffffu, s3, off);
                        }
                        __syncwarp();
                        const float invLo = 1.f / (hsel ? s1 : s0);
                        const float invHi = 1.f / (hsel ? s3 : s2);
                        // ---- coalesced SpMM over neighbors, unroll 4 ----
                        float acc0 = 0.f, acc1 = 0.f;
                        int j0 = 0;
                        for (; j0 + 4 <= cnt; j0 += 4) {
                            int   jj[4]; float al[4], ah[4], h0v[4], h1v[4];
                            #pragma unroll
                            for (int u = 0; u < 4; ++u) {
                                jj[u] = idxr[j0+u];
                                al[u] = awf[(j0+u)*4 + hsel];
                                ah[u] = awf[(j0+u)*4 + 2 + hsel];
                            }
                            #pragma unroll
                            for (int u = 0; u < 4; ++u) {
                                const float* hp = hl + (size_t)jj[u]*DD;
                                h0v[u] = __ldcg(hp + lane);
                                h1v[u] = __ldcg(hp + lane + 32);
                            }
                            #pragma unroll
                            for (int u = 0; u < 4; ++u) {
                                acc0 += al[u]*h0v[u];
                                acc1 += ah[u]*h1v[u];
                            }
                        }
                        for (; j0 < cnt; ++j0) {
                            int j = idxr[j0];
                            const float* hp = hl + (size_t)j*DD;
                            acc0 += awf[j0*4 + hsel]     * __ldcg(hp + lane);
                            acc1 += awf[j0*4 + 2 + hsel] * __ldcg(hp + lane + 32);
                        }
                        float k0 = acc0 * invLo;
                        float k1 = acc1 * invHi;
                        // ---- fused epilogue (registers -> sX) ----
                        float* xr = sX + r*DD;
                        if (l == 0) {
                            xr[lane]      = (k0 > 0.f) ? k0 : (__expf(k0) - 1.f);
                            xr[lane + 32] = (k1 > 0.f) ? k1 : (__expf(k1) - 1.f);
                        } else {
                            if (st == 0) { accR[q][0] = k0; accR[q][1] = k1; }
                            else {
                                float w = (st == 3) ? 1.f : 2.f;
                                accR[q][0] += w * k0; accR[q][1] += w * k1;
                            }
                            if (st < 3) {
                                float cc = (st == 2) ? dt : 0.5f * dt;
                                xr[lane]      = yR[q][0] + cc * k0;
                                xr[lane + 32] = yR[q][1] + cc * k1;
                            } else {
                                yR[q][0] += dt * (1.f/6.f) * accR[q][0];
                                yR[q][1] += dt * (1.f/6.f) * accR[q][1];
                                xr[lane]      = yR[q][0];
                                xr[lane + 32] = yR[q][1];
                            }
                        }
                    }
                }
            } // l
        } // st
        // ---- readout for t = s+1 ----
        for (int q = 0, r = wid; r < nrows; ++q, r += NWARP) {
            rb[lane]      = yR[q][0];
            rb[lane + 32] = yR[q][1];
            __syncwarp();
            warp_readout(rb, sB1, sW2v, bias2,
                         out + ((size_t)(b*(STEPS+1) + s + 1))*NN + base + r, lane);
            __syncwarp();
        }
    } // s
}

extern "C" void kernel_launch(void* const* d_in, const int* in_sizes, int n_in,
                              void* d_out, int out_size)
{
    const float* y0    = (const float*)d_in[0];
    const float* graph = (const float*)d_in[1];
    const float* Wg    = (const float*)d_in[2];
    const float* a_src = (const float*)d_in[3];
    const float* a_dst = (const float*)d_in[4];
    const float* W1    = (const float*)d_in[5];
    const float* b1    = (const float*)d_in[6];
    const float* W2    = (const float*)d_in[7];
    const float* b2    = (const float*)d_in[8];
    float* out = (float*)d_out;

    cudaFuncSetAttribute(ode_kernel,
                         cudaFuncAttributeMaxDynamicSharedMemorySize, SMEM_BYTES);
    prep_kernel<<<41, 256>>>(graph, W1);
    ode_kernel<<<BB*CLX, TPB, SMEM_BYTES>>>(y0, Wg, a_src, a_dst, b1, W2, b2, out);
}

// round 4
// speedup vs baseline: 1.9299x; 1.1414x over previous
#include <cuda_runtime.h>
#include <math.h>

#define BB 16
#define NN 325
#define DD 64
#define HH 4
#define STEPS 12
#define MAXD 128
#define CLX 8
#define TPB 384
#define NWARP (TPB/32)
#define RPC 41          // rows per CTA: ranks 0-6 -> 41, rank 7 -> 38
#define QSLOT 4

// ---- dynamic smem layout (float offsets) ----
#define OFF_W     0        // 2*64*64 = 8192
#define OFF_X     8192     // 41*64   = 2624
#define OFF_H     10816    // 325*64  = 20800  (full-batch h copy)
#define OFF_ED    31616    // 325*4   = 1300 (+pad)
#define OFF_AL    32920    // 12*128*4= 6144
#define OFF_ROW   39064    // 12*64   = 768
#define OFF_ES    39832    // 41*4    = 164 (+pad)
#define OFF_AS    40000    // 128
#define OFF_AD    40128    // 128
#define OFF_W2    40256    // 64
#define OFF_B1    40320    // 64
#define OFF_CNT   40384    // 41 ints (+pad)
#define OFF_IDX   40432    // 41*128 ints = 5248
#define SMEM_FLOATS 45680
#define SMEM_BYTES (SMEM_FLOATS*4)   // 182720 B

// ---------------- global scratch (static: no allocations) ----------------
__device__ float g_h  [2][BB*NN*DD];
__device__ float g_ed4[2][BB*NN*HH];    // interleaved: [node*4 + head]
__device__ float g_W1t[DD*DD];          // W1 transposed: [c*64 + k]
__device__ int   g_adj_cnt[NN];
__device__ int   g_adj_idx[NN*MAXD];

// ---------------- prep: adjacency CSR (ordered) + W1 transpose -----------
__global__ void prep_kernel(const float* __restrict__ graph,
                            const float* __restrict__ W1)
{
    int gt = blockIdx.x * blockDim.x + threadIdx.x;
    for (int i = gt; i < DD*DD; i += gridDim.x * blockDim.x)
        g_W1t[(i & 63) * DD + (i >> 6)] = W1[i];

    int gwarp = gt >> 5;
    int lane  = threadIdx.x & 31;
    if (gwarp >= NN) return;
    const int i = gwarp;
    const float* row = graph + (size_t)i * NN;
    int c = 0;
    for (int j0 = 0; j0 < NN; j0 += 32) {
        int j = j0 + lane;
        bool v = (j < NN) && (row[j] > 0.9f || j == i);
        unsigned m = __ballot_sync(0xffffffffu, v);
        if (v) {
            int pos = c + __popc(m & ((1u << lane) - 1u));
            if (pos < MAXD) g_adj_idx[i * MAXD + pos] = j;
        }
        c += __popc(m);
    }
    if (lane == 0) g_adj_cnt[i] = (c > MAXD) ? MAXD : c;
}

__device__ __forceinline__ void cluster_sync_rel()
{
    asm volatile("fence.acq_rel.cluster;" ::: "memory");  // release to L2
    asm volatile("barrier.cluster.arrive.aligned;" ::: "memory");
    asm volatile("barrier.cluster.wait.aligned;"   ::: "memory");
}

__device__ __forceinline__ float f4c(const float4& v, int kk)
{
    return (kk == 0) ? v.x : (kk == 1) ? v.y : (kk == 2) ? v.z : v.w;
}

// ---------------- readout: out = tanh(row@W1 + b1) @ W2 + b2 -------------
__device__ __forceinline__ void warp_readout(
    const float* __restrict__ rb, const float* __restrict__ sB1,
    const float* __restrict__ sW2v, float bias2,
    float* __restrict__ outp, int lane)
{
    const float4* W1t4 = reinterpret_cast<const float4*>(g_W1t);
    float s0 = sB1[lane], s1 = sB1[lane + 32];
    #pragma unroll
    for (int k4 = 0; k4 < 16; ++k4) {
        float4 yv = reinterpret_cast<const float4*>(rb)[k4];
        float4 w0 = W1t4[lane * 16 + k4];
        float4 w1 = W1t4[(lane + 32) * 16 + k4];
        s0 += yv.x*w0.x + yv.y*w0.y + yv.z*w0.z + yv.w*w0.w;
        s1 += yv.x*w1.x + yv.y*w1.y + yv.z*w1.z + yv.w*w1.w;
    }
    float t = tanhf(s0) * sW2v[lane] + tanhf(s1) * sW2v[lane + 32];
    #pragma unroll
    for (int off = 16; off; off >>= 1)
        t += __shfl_xor_sync(0xffffffffu, t, off);
    if (lane == 0) *outp = t + bias2;
}

// ---------------- main: one 8-CTA cluster per batch -----------------------
__global__ void __launch_bounds__(TPB, 1) __cluster_dims__(CLX, 1, 1)
ode_kernel(const float* __restrict__ y0,
           const float* __restrict__ Wg,
           const float* __restrict__ a_src,
           const float* __restrict__ a_dst,
           const float* __restrict__ b1,
           const float* __restrict__ W2,
           const float* __restrict__ b2,
           float* __restrict__ out)
{
    extern __shared__ float sm[];
    float* sW   = sm + OFF_W;
    float* sX   = sm + OFF_X;
    float* sH   = sm + OFF_H;
    float* sED  = sm + OFF_ED;
    float* sAl  = sm + OFF_AL;
    float* sRow = sm + OFF_ROW;
    float* sEs  = sm + OFF_ES;
    float* sAS  = sm + OFF_AS;
    float* sAD  = sm + OFF_AD;
    float* sW2v = sm + OFF_W2;
    float* sB1  = sm + OFF_B1;
    int*   sCnt = (int*)(sm + OFF_CNT);
    int*   sIdx = (int*)(sm + OFF_IDX);

    const int b    = blockIdx.x / CLX;
    const int rank = blockIdx.x % CLX;
    const int tid  = threadIdx.x;
    const int wid  = tid >> 5;
    const int lane = tid & 31;
    const int base  = rank * RPC;
    const int nrows = (rank == CLX - 1) ? (NN - base) : RPC;

    for (int i = tid; i < 2*DD*DD; i += TPB) sW[i] = Wg[i];
    for (int i = tid; i < 2*DD;    i += TPB) { sAS[i] = a_src[i]; sAD[i] = a_dst[i]; }
    for (int i = tid; i < DD;      i += TPB) { sW2v[i] = W2[i]; sB1[i] = b1[i]; }
    for (int i = tid; i < nrows;   i += TPB) sCnt[i] = g_adj_cnt[base + i];
    for (int i = tid; i < nrows*MAXD; i += TPB)
        sIdx[i] = g_adj_idx[base*MAXD + i];
    const float bias2 = b2[0];

    float* rb = sRow + wid * DD;
    const size_t bo = (size_t)b * NN * DD;

    float yR[QSLOT][2], accR[QSLOT][2];

    __syncthreads();
    // ---- init y/x + t=0 readout ----
    for (int q = 0, r = wid; r < nrows; ++q, r += NWARP) {
        const size_t ro = bo + (size_t)(base + r) * DD;
        yR[q][0] = y0[ro + lane];
        yR[q][1] = y0[ro + lane + 32];
        sX[r*DD + lane]      = yR[q][0];
        sX[r*DD + lane + 32] = yR[q][1];
        rb[lane]      = yR[q][0];
        rb[lane + 32] = yR[q][1];
        __syncwarp();
        warp_readout(rb, sB1, sW2v, bias2,
                     out + ((size_t)(b*(STEPS+1) + 0))*NN + base + r, lane);
        __syncwarp();
    }

    for (int s = 0; s < STEPS; ++s) {
        const float dt = (float)(s+1)*0.1f - (float)s*0.1f;
        for (int st = 0; st < 4; ++st) {
            for (int l = 0; l < 2; ++l) {
                __syncthreads();
                // ======= Phase A: h = x@W, e_src, e_dst (all-smem GEMM) ===
                {
                    const float* Wl = sW + l*DD*DD;
                    const int r0 = wid * 4;
                    if (r0 < nrows) {
                        int rl[4];
                        #pragma unroll
                        for (int r = 0; r < 4; ++r) {
                            int rr = r0 + r; if (rr > nrows-1) rr = nrows-1;
                            rl[r] = rr;
                        }
                        float a00=0,a01=0,a10=0,a11=0,a20=0,a21=0,a30=0,a31=0;
                        const float4* x4 = reinterpret_cast<const float4*>(sX);
                        #pragma unroll 2
                        for (int k = 0; k < DD; k += 4) {
                            float4 x0 = x4[rl[0]*16 + (k>>2)];
                            float4 x1 = x4[rl[1]*16 + (k>>2)];
                            float4 x2 = x4[rl[2]*16 + (k>>2)];
                            float4 x3 = x4[rl[3]*16 + (k>>2)];
                            #pragma unroll
                            for (int kk = 0; kk < 4; ++kk) {
                                float w0 = Wl[(k+kk)*DD + lane];
                                float w1 = Wl[(k+kk)*DD + lane + 32];
                                float c0 = f4c(x0,kk), c1 = f4c(x1,kk);
                                float c2 = f4c(x2,kk), c3 = f4c(x3,kk);
                                a00 += c0*w0; a01 += c0*w1;
                                a10 += c1*w0; a11 += c1*w1;
                                a20 += c2*w0; a21 += c2*w1;
                                a30 += c3*w0; a31 += c3*w1;
                            }
                        }
                        float accs[4][2] = {{a00,a01},{a10,a11},{a20,a21},{a30,a31}};
                        #pragma unroll
                        for (int r = 0; r < 4; ++r) {
                            if (r0 + r >= nrows) break;
                            const int row = base + r0 + r;
                            float* hp = g_h[l] + bo + (size_t)row*DD;
                            __stcg(hp + lane,      accs[r][0]);
                            __stcg(hp + lane + 32, accs[r][1]);
                            float v1 = accs[r][0]*sAS[l*DD+lane];
                            float v2 = accs[r][1]*sAS[l*DD+lane+32];
                            float v3 = accs[r][0]*sAD[l*DD+lane];
                            float v4 = accs[r][1]*sAD[l*DD+lane+32];
                            #pragma unroll
                            for (int off = 8; off; off >>= 1) {
                                v1 += __shfl_down_sync(0xffffffffu, v1, off, 16);
                                v2 += __shfl_down_sync(0xffffffffu, v2, off, 16);
                                v3 += __shfl_down_sync(0xffffffffu, v3, off, 16);
                                v4 += __shfl_down_sync(0xffffffffu, v4, off, 16);
                            }
                            if ((lane & 15) == 0) {
                                const int h0 = lane >> 4;   // 0 or 1
                                sEs[(r0 + r)*4 + h0]     = v1;
                                sEs[(r0 + r)*4 + h0 + 2] = v2;
                                float* ed = g_ed4[l] + ((size_t)b*NN + row)*4;
                                __stcg(ed + h0,     v3);
                                __stcg(ed + h0 + 2, v4);
                            }
                        }
                    }
                }
                __syncthreads();
                cluster_sync_rel();
                // ======= bulk copy: full-batch h + ed4 -> smem ============
                {
                    const float4* hg = reinterpret_cast<const float4*>(g_h[l] + bo);
                    float4* hs = reinterpret_cast<float4*>(sH);
                    #pragma unroll 4
                    for (int i = tid; i < NN*DD/4; i += TPB)
                        hs[i] = __ldcg(hg + i);
                    const float4* eg = reinterpret_cast<const float4*>(
                        g_ed4[l] + (size_t)b*NN*HH);
                    float4* es4 = reinterpret_cast<float4*>(sED);
                    for (int i = tid; i < NN; i += TPB)
                        es4[i] = __ldcg(eg + i);
                }
                __syncthreads();
                // ======= Phase B: sparse attention (all-smem) =============
                {
                    float4* aw = reinterpret_cast<float4*>(sAl) + wid * MAXD;
                    const float* awf = sAl + wid * MAXD * 4;
                    const int hsel = lane >> 4;
                    for (int q = 0, r = wid; r < nrows; ++q, r += NWARP) {
                        const int cnt = sCnt[r];
                        const int* idxr = sIdx + r * MAXD;
                        float4 esv = reinterpret_cast<const float4*>(sEs)[r];
                        float m0=-3e38f, m1=-3e38f, m2=-3e38f, m3=-3e38f;
                        for (int j0 = lane; j0 < cnt; j0 += 32) {
                            int j = idxr[j0];
                            float4 ev = reinterpret_cast<const float4*>(sED)[j];
                            float e0 = esv.x + ev.x; e0 = (e0 > 0.f) ? e0 : 0.2f*e0;
                            float e1 = esv.y + ev.y; e1 = (e1 > 0.f) ? e1 : 0.2f*e1;
                            float e2 = esv.z + ev.z; e2 = (e2 > 0.f) ? e2 : 0.2f*e2;
                            float e3 = esv.w + ev.w; e3 = (e3 > 0.f) ? e3 : 0.2f*e3;
                            aw[j0] = make_float4(e0, e1, e2, e3);
                            m0 = fmaxf(m0, e0); m1 = fmaxf(m1, e1);
                            m2 = fmaxf(m2, e2); m3 = fmaxf(m3, e3);
                        }
                        #pragma unroll
                        for (int off = 16; off; off >>= 1) {
                            m0 = fmaxf(m0, __shfl_xor_sync(0xffffffffu, m0, off));
                            m1 = fmaxf(m1, __shfl_xor_sync(0xffffffffu, m1, off));
                            m2 = fmaxf(m2, __shfl_xor_sync(0xffffffffu, m2, off));
                            m3 = fmaxf(m3, __shfl_xor_sync(0xffffffffu, m3, off));
                        }
                        float s0=0.f, s1=0.f, s2=0.f, s3=0.f;
                        for (int j0 = lane; j0 < cnt; j0 += 32) {
                            float4 v = aw[j0];
                            v.x = __expf(v.x - m0); v.y = __expf(v.y - m1);
                            v.z = __expf(v.z - m2); v.w = __expf(v.w - m3);
                            aw[j0] = v;
                            s0 += v.x; s1 += v.y; s2 += v.z; s3 += v.w;
                        }
                        #pragma unroll
                        for (int off = 16; off; off >>= 1) {
                            s0 += __shfl_xor_sync(0xffffffffu, s0, off);
                            s1 += __shfl_xor_sync(0xffffffffu, s1, off);
                            s2 += __shfl_xor_sync(0xffffffffu, s2, off);
                            s3 += __shfl_xor_sync(0xffffffffu, s3, off);
                        }
                        __syncwarp();
                        const float invLo = 1.f / (hsel ? s1 : s0);
                        const float invHi = 1.f / (hsel ? s3 : s2);
                        // ---- smem SpMM over neighbors, unroll 4 ----
                        float acc0 = 0.f, acc1 = 0.f;
                        int j0 = 0;
                        for (; j0 + 4 <= cnt; j0 += 4) {
                            float al[4], ah[4], h0v[4], h1v[4];
                            #pragma unroll
                            for (int u = 0; u < 4; ++u) {
                                int j = idxr[j0+u];
                                al[u]  = awf[(j0+u)*4 + hsel];
                                ah[u]  = awf[(j0+u)*4 + 2 + hsel];
                                h0v[u] = sH[j*DD + lane];
                                h1v[u] = sH[j*DD + lane + 32];
                            }
                            #pragma unroll
                            for (int u = 0; u < 4; ++u) {
                                acc0 += al[u]*h0v[u];
                                acc1 += ah[u]*h1v[u];
                            }
                        }
                        for (; j0 < cnt; ++j0) {
                            int j = idxr[j0];
                            acc0 += awf[j0*4 + hsel]     * sH[j*DD + lane];
                            acc1 += awf[j0*4 + 2 + hsel] * sH[j*DD + lane + 32];
                        }
                        float k0 = acc0 * invLo;
                        float k1 = acc1 * invHi;
                        // ---- fused epilogue (registers -> sX) ----
                        float* xr = sX + r*DD;
                        if (l == 0) {
                            xr[lane]      = (k0 > 0.f) ? k0 : (__expf(k0) - 1.f);
                            xr[lane + 32] = (k1 > 0.f) ? k1 : (__expf(k1) - 1.f);
                        } else {
                            if (st == 0) { accR[q][0] = k0; accR[q][1] = k1; }
                            else {
                                float w = (st == 3) ? 1.f : 2.f;
                                accR[q][0] += w * k0; accR[q][1] += w * k1;
                            }
                            if (st < 3) {
                                float cc = (st == 2) ? dt : 0.5f * dt;
                                xr[lane]      = yR[q][0] + cc * k0;
                                xr[lane + 32] = yR[q][1] + cc * k1;
                            } else {
                                yR[q][0] += dt * (1.f/6.f) * accR[q][0];
                                yR[q][1] += dt * (1.f/6.f) * accR[q][1];
                                xr[lane]      = yR[q][0];
                                xr[lane + 32] = yR[q][1];
                            }
                        }
                    }
                }
            } // l
        } // st
        // ---- readout for t = s+1 ----
        for (int q = 0, r = wid; r < nrows; ++q, r += NWARP) {
            rb[lane]      = yR[q][0];
            rb[lane + 32] = yR[q][1];
            __syncwarp();
            warp_readout(rb, sB1, sW2v, bias2,
                         out + ((size_t)(b*(STEPS+1) + s + 1))*NN + base + r, lane);
            __syncwarp();
        }
    } // s
}

extern "C" void kernel_launch(void* const* d_in, const int* in_sizes, int n_in,
                              void* d_out, int out_size)
{
    const float* y0    = (const float*)d_in[0];
    const float* graph = (const float*)d_in[1];
    const float* Wg    = (const float*)d_in[2];
    const float* a_src = (const float*)d_in[3];
    const float* a_dst = (const float*)d_in[4];
    const float* W1    = (const float*)d_in[5];
    const float* b1    = (const float*)d_in[6];
    const float* W2    = (const float*)d_in[7];
    const float* b2    = (const float*)d_in[8];
    float* out = (float*)d_out;

    cudaFuncSetAttribute(ode_kernel,
                         cudaFuncAttributeMaxDynamicSharedMemorySize, SMEM_BYTES);
    prep_kernel<<<41, 256>>>(graph, W1);
    ode_kernel<<<BB*CLX, TPB, SMEM_BYTES>>>(y0, Wg, a_src, a_dst, b1, W2, b2, out);
}

// round 5
// speedup vs baseline: 2.3004x; 1.1920x over previous
#include <cuda_runtime.h>
#include <math.h>

#define BB 16
#define NN 325
#define DD 64
#define HH 4
#define STEPS 12
#define MAXD 128
#define CLX 8
#define TPB 512
#define NWARP (TPB/32)   // 16
#define RPC 41           // rows per CTA: ranks 0-6 -> 41, rank 7 -> 38
#define QSLOT 3          // ceil(41/16)
#define ROWA 3           // GEMM rows per warp (14 warps cover 41)

// ---- dynamic smem layout (float offsets), float4 areas 16B-aligned ----
#define OFF_W     0        // 8192
#define OFF_X     8192     // 2624
#define OFF_H     10816    // 20800
#define OFF_ED    31616    // 1300 (+pad 12)
#define OFF_AL    32928    // 16*128*4 = 8192
#define OFF_ROW   41120    // 16*64 = 1024
#define OFF_ES    42144    // 41*4 = 164 (+pad)
#define OFF_AS    42312    // 128
#define OFF_AD    42440    // 128
#define OFF_W2    42568    // 64
#define OFF_B1    42632    // 64
#define OFF_CNT   42696    // 48
#define OFF_IDX   42744    // 5248
#define SMEM_FLOATS 47992
#define SMEM_BYTES (SMEM_FLOATS*4)   // 191968 B

// ---------------- global scratch (static: no allocations) ----------------
__device__ float g_h  [2][BB*NN*DD];
__device__ float g_ed4[2][BB*NN*HH];    // interleaved: [node*4 + head]
__device__ float g_W1t[DD*DD];          // W1 transposed: [c*64 + k]
__device__ int   g_adj_cnt[NN];
__device__ int   g_adj_idx[NN*MAXD];

// ---------------- prep: adjacency CSR (ordered) + W1 transpose -----------
__global__ void prep_kernel(const float* __restrict__ graph,
                            const float* __restrict__ W1)
{
    int gt = blockIdx.x * blockDim.x + threadIdx.x;
    for (int i = gt; i < DD*DD; i += gridDim.x * blockDim.x)
        g_W1t[(i & 63) * DD + (i >> 6)] = W1[i];

    int gwarp = gt >> 5;
    int lane  = threadIdx.x & 31;
    if (gwarp >= NN) return;
    const int i = gwarp;
    const float* row = graph + (size_t)i * NN;
    int c = 0;
    for (int j0 = 0; j0 < NN; j0 += 32) {
        int j = j0 + lane;
        bool v = (j < NN) && (row[j] > 0.9f || j == i);
        unsigned m = __ballot_sync(0xffffffffu, v);
        if (v) {
            int pos = c + __popc(m & ((1u << lane) - 1u));
            if (pos < MAXD) g_adj_idx[i * MAXD + pos] = j;
        }
        c += __popc(m);
    }
    if (lane == 0) g_adj_cnt[i] = (c > MAXD) ? MAXD : c;
}

__device__ __forceinline__ void cluster_sync_rel()
{
    asm volatile("fence.acq_rel.cluster;" ::: "memory");
    asm volatile("barrier.cluster.arrive.aligned;" ::: "memory");
    asm volatile("barrier.cluster.wait.aligned;"   ::: "memory");
}

__device__ __forceinline__ float f4c(const float4& v, int kk)
{
    return (kk == 0) ? v.x : (kk == 1) ? v.y : (kk == 2) ? v.z : v.w;
}

// ---------------- readout: out = tanh(row@W1 + b1) @ W2 + b2 -------------
__device__ __forceinline__ void warp_readout(
    const float* __restrict__ rb, const float* __restrict__ sB1,
    const float* __restrict__ sW2v, float bias2,
    float* __restrict__ outp, int lane)
{
    const float4* W1t4 = reinterpret_cast<const float4*>(g_W1t);
    float s0 = sB1[lane], s1 = sB1[lane + 32];
    #pragma unroll
    for (int k4 = 0; k4 < 16; ++k4) {
        float4 yv = reinterpret_cast<const float4*>(rb)[k4];
        float4 w0 = W1t4[lane * 16 + k4];
        float4 w1 = W1t4[(lane + 32) * 16 + k4];
        s0 += yv.x*w0.x + yv.y*w0.y + yv.z*w0.z + yv.w*w0.w;
        s1 += yv.x*w1.x + yv.y*w1.y + yv.z*w1.z + yv.w*w1.w;
    }
    float t = tanhf(s0) * sW2v[lane] + tanhf(s1) * sW2v[lane + 32];
    #pragma unroll
    for (int off = 16; off; off >>= 1)
        t += __shfl_xor_sync(0xffffffffu, t, off);
    if (lane == 0) *outp = t + bias2;
}

// ---------------- main: one 8-CTA cluster per batch -----------------------
__global__ void __launch_bounds__(TPB, 1) __cluster_dims__(CLX, 1, 1)
ode_kernel(const float* __restrict__ y0,
           const float* __restrict__ Wg,
           const float* __restrict__ a_src,
           const float* __restrict__ a_dst,
           const float* __restrict__ b1,
           const float* __restrict__ W2,
           const float* __restrict__ b2,
           float* __restrict__ out)
{
    extern __shared__ float sm[];
    float* sW   = sm + OFF_W;
    float* sX   = sm + OFF_X;
    float* sH   = sm + OFF_H;
    float* sED  = sm + OFF_ED;
    float* sAl  = sm + OFF_AL;
    float* sRow = sm + OFF_ROW;
    float* sEs  = sm + OFF_ES;
    float* sAS  = sm + OFF_AS;
    float* sAD  = sm + OFF_AD;
    float* sW2v = sm + OFF_W2;
    float* sB1  = sm + OFF_B1;
    int*   sCnt = (int*)(sm + OFF_CNT);
    int*   sIdx = (int*)(sm + OFF_IDX);

    const int b    = blockIdx.x / CLX;
    const int rank = blockIdx.x % CLX;
    const int tid  = threadIdx.x;
    const int wid  = tid >> 5;
    const int lane = tid & 31;
    const int hsel = lane >> 3;          // head owned by this lane (8-lane groups)
    const int base  = rank * RPC;
    const int nrows = (rank == CLX - 1) ? (NN - base) : RPC;

    for (int i = tid; i < 2*DD*DD; i += TPB) sW[i] = Wg[i];
    for (int i = tid; i < 2*DD;    i += TPB) { sAS[i] = a_src[i]; sAD[i] = a_dst[i]; }
    for (int i = tid; i < DD;      i += TPB) { sW2v[i] = W2[i]; sB1[i] = b1[i]; }
    for (int i = tid; i < nrows;   i += TPB) sCnt[i] = g_adj_cnt[base + i];
    for (int i = tid; i < nrows*MAXD; i += TPB)
        sIdx[i] = g_adj_idx[base*MAXD + i];
    const float bias2 = b2[0];

    float* rb = sRow + wid * DD;
    const size_t bo = (size_t)b * NN * DD;

    float yR[QSLOT][2], accR[QSLOT][2];

    __syncthreads();
    // ---- init y/x + t=0 readout (lane owns channels 2l, 2l+1) ----
    for (int q = 0, r = wid; r < nrows; ++q, r += NWARP) {
        const size_t ro = bo + (size_t)(base + r) * DD;
        float2 yv = *reinterpret_cast<const float2*>(y0 + ro + 2*lane);
        yR[q][0] = yv.x; yR[q][1] = yv.y;
        *reinterpret_cast<float2*>(sX + r*DD + 2*lane) = yv;
        *reinterpret_cast<float2*>(rb + 2*lane) = yv;
        __syncwarp();
        warp_readout(rb, sB1, sW2v, bias2,
                     out + ((size_t)(b*(STEPS+1) + 0))*NN + base + r, lane);
        __syncwarp();
    }

    for (int s = 0; s < STEPS; ++s) {
        const float dt = (float)(s+1)*0.1f - (float)s*0.1f;
        for (int st = 0; st < 4; ++st) {
            for (int l = 0; l < 2; ++l) {
                __syncthreads();
                // ======= Phase A: h = x@W, e_src, e_dst (all-smem GEMM) ===
                {
                    const float* Wl = sW + l*DD*DD;
                    const float2* w2p = reinterpret_cast<const float2*>(Wl);
                    const int r0 = wid * ROWA;
                    if (r0 < nrows) {
                        int rl[ROWA];
                        #pragma unroll
                        for (int r = 0; r < ROWA; ++r) {
                            int rr = r0 + r; if (rr > nrows-1) rr = nrows-1;
                            rl[r] = rr;
                        }
                        float a0x=0,a0y=0,a1x=0,a1y=0,a2x=0,a2y=0;
                        const float4* x4 = reinterpret_cast<const float4*>(sX);
                        #pragma unroll 4
                        for (int k4 = 0; k4 < 16; ++k4) {
                            float4 x0 = x4[rl[0]*16 + k4];
                            float4 x1 = x4[rl[1]*16 + k4];
                            float4 x2 = x4[rl[2]*16 + k4];
                            #pragma unroll
                            for (int kk = 0; kk < 4; ++kk) {
                                float2 w = w2p[(k4*4+kk)*32 + lane];
                                float c0 = f4c(x0,kk), c1 = f4c(x1,kk), c2 = f4c(x2,kk);
                                a0x += c0*w.x; a0y += c0*w.y;
                                a1x += c1*w.x; a1y += c1*w.y;
                                a2x += c2*w.x; a2y += c2*w.y;
                            }
                        }
                        float ax[ROWA] = {a0x, a1x, a2x};
                        float ay[ROWA] = {a0y, a1y, a2y};
                        #pragma unroll
                        for (int r = 0; r < ROWA; ++r) {
                            if (r0 + r >= nrows) break;
                            const int row = base + r0 + r;
                            float* hp = g_h[l] + bo + (size_t)row*DD;
                            float2 hv = make_float2(ax[r], ay[r]);
                            __stcg(reinterpret_cast<float2*>(hp + 2*lane), hv);
                            float ves = ax[r]*sAS[l*DD + 2*lane] + ay[r]*sAS[l*DD + 2*lane + 1];
                            float ved = ax[r]*sAD[l*DD + 2*lane] + ay[r]*sAD[l*DD + 2*lane + 1];
                            #pragma unroll
                            for (int off = 4; off; off >>= 1) {
                                ves += __shfl_down_sync(0xffffffffu, ves, off, 8);
                                ved += __shfl_down_sync(0xffffffffu, ved, off, 8);
                            }
                            if ((lane & 7) == 0) {
                                sEs[(r0 + r)*4 + hsel] = ves;
                                __stcg(g_ed4[l] + ((size_t)b*NN + row)*4 + hsel, ved);
                            }
                        }
                    }
                }
                cluster_sync_rel();
                // ======= bulk copy: full-batch h + ed4 -> smem ============
                {
                    const float4* hg = reinterpret_cast<const float4*>(g_h[l] + bo);
                    float4* hs = reinterpret_cast<float4*>(sH);
                    #pragma unroll 4
                    for (int i = tid; i < NN*DD/4; i += TPB)
                        hs[i] = __ldcg(hg + i);
                    const float4* eg = reinterpret_cast<const float4*>(
                        g_ed4[l] + (size_t)b*NN*HH);
                    float4* es4 = reinterpret_cast<float4*>(sED);
                    for (int i = tid; i < NN; i += TPB)
                        es4[i] = __ldcg(eg + i);
                }
                __syncthreads();
                // ======= Phase B: sparse attention (all-smem) =============
                {
                    float4* aw = reinterpret_cast<float4*>(sAl) + wid * MAXD;
                    const float* awf = sAl + wid * MAXD * 4;
                    const float2* h2 = reinterpret_cast<const float2*>(sH);
                    for (int q = 0, r = wid; r < nrows; ++q, r += NWARP) {
                        const int cnt = sCnt[r];
                        const int* idxr = sIdx + r * MAXD;
                        float4 esv = reinterpret_cast<const float4*>(sEs)[r];
                        float m0=-3e38f, m1=-3e38f, m2=-3e38f, m3=-3e38f;
                        for (int j0 = lane; j0 < cnt; j0 += 32) {
                            int j = idxr[j0];
                            float4 ev = reinterpret_cast<const float4*>(sED)[j];
                            float e0 = esv.x + ev.x; e0 = (e0 > 0.f) ? e0 : 0.2f*e0;
                            float e1 = esv.y + ev.y; e1 = (e1 > 0.f) ? e1 : 0.2f*e1;
                            float e2 = esv.z + ev.z; e2 = (e2 > 0.f) ? e2 : 0.2f*e2;
                            float e3 = esv.w + ev.w; e3 = (e3 > 0.f) ? e3 : 0.2f*e3;
                            aw[j0] = make_float4(e0, e1, e2, e3);
                            m0 = fmaxf(m0, e0); m1 = fmaxf(m1, e1);
                            m2 = fmaxf(m2, e2); m3 = fmaxf(m3, e3);
                        }
                        #pragma unroll
                        for (int off = 16; off; off >>= 1) {
                            m0 = fmaxf(m0, __shfl_xor_sync(0xffffffffu, m0, off));
                            m1 = fmaxf(m1, __shfl_xor_sync(0xffffffffu, m1, off));
                            m2 = fmaxf(m2, __shfl_xor_sync(0xffffffffu, m2, off));
                            m3 = fmaxf(m3, __shfl_xor_sync(0xffffffffu, m3, off));
                        }
                        float s0=0.f, s1=0.f, s2=0.f, s3=0.f;
                        for (int j0 = lane; j0 < cnt; j0 += 32) {
                            float4 v = aw[j0];
                            v.x = __expf(v.x - m0); v.y = __expf(v.y - m1);
                            v.z = __expf(v.z - m2); v.w = __expf(v.w - m3);
                            aw[j0] = v;
                            s0 += v.x; s1 += v.y; s2 += v.z; s3 += v.w;
                        }
                        #pragma unroll
                        for (int off = 16; off; off >>= 1) {
                            s0 += __shfl_xor_sync(0xffffffffu, s0, off);
                            s1 += __shfl_xor_sync(0xffffffffu, s1, off);
                            s2 += __shfl_xor_sync(0xffffffffu, s2, off);
                            s3 += __shfl_xor_sync(0xffffffffu, s3, off);
                        }
                        __syncwarp();
                        const float ssum = (hsel == 0) ? s0 : (hsel == 1) ? s1
                                         : (hsel == 2) ? s2 : s3;
                        const float inv = 1.f / ssum;
                        // ---- smem SpMM over neighbors (float2, same head) ----
                        float acc0 = 0.f, acc1 = 0.f;
                        int j0 = 0;
                        for (; j0 + 4 <= cnt; j0 += 4) {
                            float al[4]; float2 hv[4];
                            #pragma unroll
                            for (int u = 0; u < 4; ++u) {
                                int j = idxr[j0+u];
                                al[u] = awf[(j0+u)*4 + hsel];
                                hv[u] = h2[j*32 + lane];
                            }
                            #pragma unroll
                            for (int u = 0; u < 4; ++u) {
                                acc0 += al[u]*hv[u].x;
                                acc1 += al[u]*hv[u].y;
                            }
                        }
                        for (; j0 < cnt; ++j0) {
                            int j = idxr[j0];
                            float a = awf[j0*4 + hsel];
                            float2 hv = h2[j*32 + lane];
                            acc0 += a*hv.x; acc1 += a*hv.y;
                        }
                        float k0 = acc0 * inv;
                        float k1 = acc1 * inv;
                        // ---- fused epilogue (registers -> sX) ----
                        float2* xr2 = reinterpret_cast<float2*>(sX + r*DD) + lane;
                        if (l == 0) {
                            float2 xv;
                            xv.x = (k0 > 0.f) ? k0 : (__expf(k0) - 1.f);
                            xv.y = (k1 > 0.f) ? k1 : (__expf(k1) - 1.f);
                            *xr2 = xv;
                        } else {
                            if (st == 0) { accR[q][0] = k0; accR[q][1] = k1; }
                            else {
                                float w = (st == 3) ? 1.f : 2.f;
                                accR[q][0] += w * k0; accR[q][1] += w * k1;
                            }
                            if (st < 3) {
                                float cc = (st == 2) ? dt : 0.5f * dt;
                                *xr2 = make_float2(yR[q][0] + cc * k0,
                                                   yR[q][1] + cc * k1);
                            } else {
                                yR[q][0] += dt * (1.f/6.f) * accR[q][0];
                                yR[q][1] += dt * (1.f/6.f) * accR[q][1];
                                *xr2 = make_float2(yR[q][0], yR[q][1]);
                            }
                        }
                    }
                }
            } // l
        } // st
        // ---- readout for t = s+1 ----
        for (int q = 0, r = wid; r < nrows; ++q, r += NWARP) {
            *reinterpret_cast<float2*>(rb + 2*lane) =
                make_float2(yR[q][0], yR[q][1]);
            __syncwarp();
            warp_readout(rb, sB1, sW2v, bias2,
                         out + ((size_t)(b*(STEPS+1) + s + 1))*NN + base + r, lane);
            __syncwarp();
        }
    } // s
}

extern "C" void kernel_launch(void* const* d_in, const int* in_sizes, int n_in,
                              void* d_out, int out_size)
{
    const float* y0    = (const float*)d_in[0];
    const float* graph = (const float*)d_in[1];
    const float* Wg    = (const float*)d_in[2];
    const float* a_src = (const float*)d_in[3];
    const float* a_dst = (const float*)d_in[4];
    const float* W1    = (const float*)d_in[5];
    const float* b1    = (const float*)d_in[6];
    const float* W2    = (const float*)d_in[7];
    const float* b2    = (const float*)d_in[8];
    float* out = (float*)d_out;

    cudaFuncSetAttribute(ode_kernel,
                         cudaFuncAttributeMaxDynamicSharedMemorySize, SMEM_BYTES);
    prep_kernel<<<41, 256>>>(graph, W1);
    ode_kernel<<<BB*CLX, TPB, SMEM_BYTES>>>(y0, Wg, a_src, a_dst, b1, W2, b2, out);
}

// round 7
// speedup vs baseline: 2.3875x; 1.0378x over previous
#include <cuda_runtime.h>
#include <cstdint>
#include <math.h>

#define BB 16
#define NN 325
#define DD 64
#define HH 4
#define STEPS 12
#define MAXD 64
#define CLX 8
#define TPB 768
#define NWARP (TPB/32)   // 24
#define RPC 41           // rows per CTA: ranks 0-6 -> 41, rank 7 -> 38
#define QSLOT 2          // ceil(41/24)
#define ROWA 2           // GEMM rows per warp (21 warps cover 41)

// ---- dynamic smem layout (float offsets), float4 areas 16B-aligned ----
#define OFF_W     0        // 8192
#define OFF_X     8192     // 2624
#define OFF_H     10816    // 20800
#define OFF_ED    31616    // 1312
#define OFF_AL    32928    // 24*2*64*4 = 12288  (per warp, per row-slot)
#define OFF_ROW   45216    // 24*64 = 1536
#define OFF_ES    46752    // 41*4 = 164 (+pad 12)
#define OFF_WMAX  46928    // 24*4 = 96
#define OFF_AS    47024    // 128
#define OFF_AD    47152    // 128
#define OFF_W2    47280    // 64
#define OFF_B1    47344    // 64
#define OFF_CNT   47408    // 48
#define OFF_IDX   47456    // 41*64 = 2624
#define SMEM_FLOATS 50080
#define SMEM_BYTES (SMEM_FLOATS*4)   // 200320 B

// ---------------- global scratch (static: no allocations) ----------------
__device__ float g_h  [2][BB*NN*DD];
__device__ float g_ed4[2][BB*NN*HH];    // interleaved: [node*4 + head]
__device__ float g_W1t[DD*DD];          // W1 transposed: [c*64 + k]
__device__ int   g_adj_cnt[NN];
__device__ int   g_adj_idx[NN*MAXD];

// ---------------- prep: adjacency CSR (ordered) + W1 transpose -----------
__global__ void prep_kernel(const float* __restrict__ graph,
                            const float* __restrict__ W1)
{
    int gt = blockIdx.x * blockDim.x + threadIdx.x;
    for (int i = gt; i < DD*DD; i += gridDim.x * blockDim.x)
        g_W1t[(i & 63) * DD + (i >> 6)] = W1[i];

    int gwarp = gt >> 5;
    int lane  = threadIdx.x & 31;
    if (gwarp >= NN) return;
    const int i = gwarp;
    const float* row = graph + (size_t)i * NN;
    int c = 0;
    for (int j0 = 0; j0 < NN; j0 += 32) {
        int j = j0 + lane;
        bool v = (j < NN) && (row[j] > 0.9f || j == i);
        unsigned m = __ballot_sync(0xffffffffu, v);
        if (v) {
            int pos = c + __popc(m & ((1u << lane) - 1u));
            if (pos < MAXD) g_adj_idx[i * MAXD + pos] = j;
        }
        c += __popc(m);
    }
    if (lane == 0) g_adj_cnt[i] = (c > MAXD) ? MAXD : c;
}

__device__ __forceinline__ void cluster_sync_rel()
{
    asm volatile("fence.acq_rel.cluster;" ::: "memory");
    asm volatile("barrier.cluster.arrive.aligned;" ::: "memory");
    asm volatile("barrier.cluster.wait.aligned;"   ::: "memory");
}

__device__ __forceinline__ void cp_async16(unsigned int saddr, const void* gptr)
{
    asm volatile("cp.async.cg.shared.global [%0], [%1], 16;"
                 :: "r"(saddr), "l"(gptr) : "memory");
}
__device__ __forceinline__ void cp_async_commit()
{
    asm volatile("cp.async.commit_group;" ::: "memory");
}
__device__ __forceinline__ void cp_async_wait_all()
{
    asm volatile("cp.async.wait_group 0;" ::: "memory");
}

__device__ __forceinline__ float f4c(const float4& v, int kk)
{
    return (kk == 0) ? v.x : (kk == 1) ? v.y : (kk == 2) ? v.z : v.w;
}

// ---------------- readout: out = tanh(row@W1 + b1) @ W2 + b2 -------------
__device__ __forceinline__ void warp_readout(
    const float* __restrict__ rb, const float* __restrict__ sB1,
    const float* __restrict__ sW2v, float bias2,
    float* __restrict__ outp, int lane)
{
    const float4* W1t4 = reinterpret_cast<const float4*>(g_W1t);
    float s0 = sB1[lane], s1 = sB1[lane + 32];
    #pragma unroll
    for (int k4 = 0; k4 < 16; ++k4) {
        float4 yv = reinterpret_cast<const float4*>(rb)[k4];
        float4 w0 = W1t4[lane * 16 + k4];
        float4 w1 = W1t4[(lane + 32) * 16 + k4];
        s0 += yv.x*w0.x + yv.y*w0.y + yv.z*w0.z + yv.w*w0.w;
        s1 += yv.x*w1.x + yv.y*w1.y + yv.z*w1.z + yv.w*w1.w;
    }
    float t = tanhf(s0) * sW2v[lane] + tanhf(s1) * sW2v[lane + 32];
    #pragma unroll
    for (int off = 16; off; off >>= 1)
        t += __shfl_xor_sync(0xffffffffu, t, off);
    if (lane == 0) *outp = t + bias2;
}

// ---------------- main: one 8-CTA cluster per batch -----------------------
__global__ void __launch_bounds__(TPB, 1) __cluster_dims__(CLX, 1, 1)
ode_kernel(const float* __restrict__ y0,
           const float* __restrict__ Wg,
           const float* __restrict__ a_src,
           const float* __restrict__ a_dst,
           const float* __restrict__ b1,
           const float* __restrict__ W2,
           const float* __restrict__ b2,
           float* __restrict__ out)
{
    extern __shared__ float sm[];
    float* sW    = sm + OFF_W;
    float* sX    = sm + OFF_X;
    float* sH    = sm + OFF_H;
    float* sED   = sm + OFF_ED;
    float* sAl   = sm + OFF_AL;
    float* sRow  = sm + OFF_ROW;
    float* sEs   = sm + OFF_ES;
    float* sWMax = sm + OFF_WMAX;
    float* sAS   = sm + OFF_AS;
    float* sAD   = sm + OFF_AD;
    float* sW2v  = sm + OFF_W2;
    float* sB1   = sm + OFF_B1;
    int*   sCnt  = (int*)(sm + OFF_CNT);
    int*   sIdx  = (int*)(sm + OFF_IDX);
    const unsigned int sHu32 =
        (unsigned int)__cvta_generic_to_shared(sH);

    const int b    = blockIdx.x / CLX;
    const int rank = blockIdx.x % CLX;
    const int tid  = threadIdx.x;
    const int wid  = tid >> 5;
    const int lane = tid & 31;
    const int hsel = lane >> 3;          // head owned by this lane
    const int base  = rank * RPC;
    const int nrows = (rank == CLX - 1) ? (NN - base) : RPC;

    for (int i = tid; i < 2*DD*DD; i += TPB) sW[i] = Wg[i];
    for (int i = tid; i < 2*DD;    i += TPB) { sAS[i] = a_src[i]; sAD[i] = a_dst[i]; }
    for (int i = tid; i < DD;      i += TPB) { sW2v[i] = W2[i]; sB1[i] = b1[i]; }
    for (int i = tid; i < nrows;   i += TPB) sCnt[i] = g_adj_cnt[base + i];
    for (int i = tid; i < nrows*MAXD; i += TPB)
        sIdx[i] = g_adj_idx[base*MAXD + i];
    const float bias2 = b2[0];

    float* rb = sRow + wid * DD;
    const size_t bo = (size_t)b * NN * DD;

    float yR[QSLOT][2], accR[QSLOT][2], invR[QSLOT];

    __syncthreads();
    // ---- init y/x + t=0 readout (lane owns channels 2l, 2l+1) ----
    for (int q = 0, r = wid; r < nrows; ++q, r += NWARP) {
        const size_t ro = bo + (size_t)(base + r) * DD;
        float2 yv = *reinterpret_cast<const float2*>(y0 + ro + 2*lane);
        yR[q][0] = yv.x; yR[q][1] = yv.y;
        *reinterpret_cast<float2*>(sX + r*DD + 2*lane) = yv;
        *reinterpret_cast<float2*>(rb + 2*lane) = yv;
        __syncwarp();
        warp_readout(rb, sB1, sW2v, bias2,
                     out + ((size_t)(b*(STEPS+1) + 0))*NN + base + r, lane);
        __syncwarp();
    }

    for (int s = 0; s < STEPS; ++s) {
        const float dt = (float)(s+1)*0.1f - (float)s*0.1f;
        for (int st = 0; st < 4; ++st) {
            for (int l = 0; l < 2; ++l) {
                __syncthreads();   // sX from prev phase B visible to all warps
                // ======= Phase A: h = x@W, e_src, e_dst (all-smem GEMM) ===
                {
                    const float* Wl = sW + l*DD*DD;
                    const float2* w2p = reinterpret_cast<const float2*>(Wl);
                    const int r0 = wid * ROWA;
                    if (r0 < nrows) {
                        int rl0 = r0;
                        int rl1 = (r0 + 1 > nrows-1) ? nrows-1 : r0 + 1;
                        float a0x=0,a0y=0,a1x=0,a1y=0;
                        const float4* x4 = reinterpret_cast<const float4*>(sX);
                        #pragma unroll 4
                        for (int k4 = 0; k4 < 16; ++k4) {
                            float4 x0 = x4[rl0*16 + k4];
                            float4 x1 = x4[rl1*16 + k4];
                            #pragma unroll
                            for (int kk = 0; kk < 4; ++kk) {
                                float2 w = w2p[(k4*4+kk)*32 + lane];
                                float c0 = f4c(x0,kk), c1 = f4c(x1,kk);
                                a0x += c0*w.x; a0y += c0*w.y;
                                a1x += c1*w.x; a1y += c1*w.y;
                            }
                        }
                        float ax[ROWA] = {a0x, a1x};
                        float ay[ROWA] = {a0y, a1y};
                        #pragma unroll
                        for (int r = 0; r < ROWA; ++r) {
                            if (r0 + r >= nrows) break;
                            const int row = base + r0 + r;
                            float* hp = g_h[l] + bo + (size_t)row*DD;
                            __stcg(reinterpret_cast<float2*>(hp + 2*lane),
                                   make_float2(ax[r], ay[r]));
                            float ves = ax[r]*sAS[l*DD + 2*lane] + ay[r]*sAS[l*DD + 2*lane + 1];
                            float ved = ax[r]*sAD[l*DD + 2*lane] + ay[r]*sAD[l*DD + 2*lane + 1];
                            #pragma unroll
                            for (int off = 4; off; off >>= 1) {
                                ves += __shfl_down_sync(0xffffffffu, ves, off, 8);
                                ved += __shfl_down_sync(0xffffffffu, ved, off, 8);
                            }
                            if ((lane & 7) == 0) {
                                sEs[(r0 + r)*4 + hsel] = ves;
                                __stcg(g_ed4[l] + ((size_t)b*NN + row)*4 + hsel, ved);
                            }
                        }
                    }
                }
                cluster_sync_rel();
                // ======= async bulk copy of h (overlapped with softmax) ===
                {
                    const float4* hg = reinterpret_cast<const float4*>(g_h[l] + bo);
                    #pragma unroll 7
                    for (int i = tid; i < NN*DD/4; i += TPB)
                        cp_async16(sHu32 + i*16, hg + i);
                    cp_async_commit();
                }
                // ======= ED copy + per-head global max =====================
                {
                    float4 mv = make_float4(-3e38f, -3e38f, -3e38f, -3e38f);
                    if (tid < NN) {
                        float4 ev = __ldcg(reinterpret_cast<const float4*>(
                            g_ed4[l] + (size_t)b*NN*HH) + tid);
                        reinterpret_cast<float4*>(sED)[tid] = ev;
                        mv = ev;
                    }
                    #pragma unroll
                    for (int off = 16; off; off >>= 1) {
                        mv.x = fmaxf(mv.x, __shfl_xor_sync(0xffffffffu, mv.x, off));
                        mv.y = fmaxf(mv.y, __shfl_xor_sync(0xffffffffu, mv.y, off));
                        mv.z = fmaxf(mv.z, __shfl_xor_sync(0xffffffffu, mv.z, off));
                        mv.w = fmaxf(mv.w, __shfl_xor_sync(0xffffffffu, mv.w, off));
                    }
                    if (lane == 0)
                        reinterpret_cast<float4*>(sWMax)[wid] = mv;
                }
                __syncthreads();
                // ======= softmax (single fused pass; global-max shift) ====
                {
                    float4 mg = (lane < NWARP)
                        ? reinterpret_cast<const float4*>(sWMax)[lane]
                        : make_float4(-3e38f, -3e38f, -3e38f, -3e38f);
                    #pragma unroll
                    for (int off = 16; off; off >>= 1) {
                        mg.x = fmaxf(mg.x, __shfl_xor_sync(0xffffffffu, mg.x, off));
                        mg.y = fmaxf(mg.y, __shfl_xor_sync(0xffffffffu, mg.y, off));
                        mg.z = fmaxf(mg.z, __shfl_xor_sync(0xffffffffu, mg.z, off));
                        mg.w = fmaxf(mg.w, __shfl_xor_sync(0xffffffffu, mg.w, off));
                    }
                    for (int q = 0, r = wid; r < nrows; ++q, r += NWARP) {
                        const int cnt = sCnt[r];
                        const int* idxr = sIdx + r * MAXD;
                        float4* aw = reinterpret_cast<float4*>(sAl)
                                   + (wid*QSLOT + q) * MAXD;
                        float4 esv = reinterpret_cast<const float4*>(sEs)[r];
                        // row shift: leaky(es + global-max ed) >= all e
                        float4 sh;
                        sh.x = esv.x + mg.x; sh.x = fmaxf(sh.x, 0.2f*sh.x);
                        sh.y = esv.y + mg.y; sh.y = fmaxf(sh.y, 0.2f*sh.y);
                        sh.z = esv.z + mg.z; sh.z = fmaxf(sh.z, 0.2f*sh.z);
                        sh.w = esv.w + mg.w; sh.w = fmaxf(sh.w, 0.2f*sh.w);
                        float s0=0.f, s1=0.f, s2=0.f, s3=0.f;
                        for (int j0 = lane; j0 < cnt; j0 += 32) {
                            int j = idxr[j0];
                            float4 ev = reinterpret_cast<const float4*>(sED)[j];
                            float e0 = esv.x + ev.x; e0 = fmaxf(e0, 0.2f*e0);
                            float e1 = esv.y + ev.y; e1 = fmaxf(e1, 0.2f*e1);
                            float e2 = esv.z + ev.z; e2 = fmaxf(e2, 0.2f*e2);
                            float e3 = esv.w + ev.w; e3 = fmaxf(e3, 0.2f*e3);
                            float p0 = __expf(e0 - sh.x);
                            float p1 = __expf(e1 - sh.y);
                            float p2 = __expf(e2 - sh.z);
                            float p3 = __expf(e3 - sh.w);
                            aw[j0] = make_float4(p0, p1, p2, p3);
                            s0 += p0; s1 += p1; s2 += p2; s3 += p3;
                        }
                        #pragma unroll
                        for (int off = 16; off; off >>= 1) {
                            s0 += __shfl_xor_sync(0xffffffffu, s0, off);
                            s1 += __shfl_xor_sync(0xffffffffu, s1, off);
                            s2 += __shfl_xor_sync(0xffffffffu, s2, off);
                            s3 += __shfl_xor_sync(0xffffffffu, s3, off);
                        }
                        const float ssum = (hsel == 0) ? s0 : (hsel == 1) ? s1
                                         : (hsel == 2) ? s2 : s3;
                        invR[q] = 1.f / ssum;
                    }
                }
                cp_async_wait_all();
                __syncthreads();
                // ======= Phase B: SpMM (all-smem) + fused epilogue ========
                {
                    const float2* h2 = reinterpret_cast<const float2*>(sH);
                    for (int q = 0, r = wid; r < nrows; ++q, r += NWARP) {
                        const int cnt = sCnt[r];
                        const int* idxr = sIdx + r * MAXD;
                        const float* awf = sAl + (wid*QSLOT + q) * MAXD * 4;
                        float acc0 = 0.f, acc1 = 0.f;
                        int j0 = 0;
                        for (; j0 + 4 <= cnt; j0 += 4) {
                            float al[4]; float2 hv[4];
                            #pragma unroll
                            for (int u = 0; u < 4; ++u) {
                                int j = idxr[j0+u];
                                al[u] = awf[(j0+u)*4 + hsel];
                                hv[u] = h2[j*32 + lane];
                            }
                            #pragma unroll
                            for (int u = 0; u < 4; ++u) {
                                acc0 += al[u]*hv[u].x;
                                acc1 += al[u]*hv[u].y;
                            }
                        }
                        for (; j0 < cnt; ++j0) {
                            int j = idxr[j0];
                            float a = awf[j0*4 + hsel];
                            float2 hv = h2[j*32 + lane];
                            acc0 += a*hv.x; acc1 += a*hv.y;
                        }
                        float k0 = acc0 * invR[q];
                        float k1 = acc1 * invR[q];
                        // ---- fused epilogue (registers -> sX) ----
                        float2* xr2 = reinterpret_cast<float2*>(sX + r*DD) + lane;
                        if (l == 0) {
                            float2 xv;
                            xv.x = (k0 > 0.f) ? k0 : (__expf(k0) - 1.f);
                            xv.y = (k1 > 0.f) ? k1 : (__expf(k1) - 1.f);
                            *xr2 = xv;
                        } else {
                            if (st == 0) { accR[q][0] = k0; accR[q][1] = k1; }
                            else {
                                float w = (st == 3) ? 1.f : 2.f;
                                accR[q][0] += w * k0; accR[q][1] += w * k1;
                            }
                            if (st < 3) {
                                float cc = (st == 2) ? dt : 0.5f * dt;
                                *xr2 = make_float2(yR[q][0] + cc * k0,
                                                   yR[q][1] + cc * k1);
                            } else {
                                yR[q][0] += dt * (1.f/6.f) * accR[q][0];
                                yR[q][1] += dt * (1.f/6.f) * accR[q][1];
                                *xr2 = make_float2(yR[q][0], yR[q][1]);
                            }
                        }
                    }
                }
            } // l
        } // st
        // ---- readout for t = s+1 ----
        for (int q = 0, r = wid; r < nrows; ++q, r += NWARP) {
            *reinterpret_cast<float2*>(rb + 2*lane) =
                make_float2(yR[q][0], yR[q][1]);
            __syncwarp();
            warp_readout(rb, sB1, sW2v, bias2,
                         out + ((size_t)(b*(STEPS+1) + s + 1))*NN + base + r, lane);
            __syncwarp();
        }
    } // s
}

extern "C" void kernel_launch(void* const* d_in, const int* in_sizes, int n_in,
                              void* d_out, int out_size)
{
    const float* y0    = (const float*)d_in[0];
    const float* graph = (const float*)d_in[1];
    const float* Wg    = (const float*)d_in[2];
    const float* a_src = (const float*)d_in[3];
    const float* a_dst = (const float*)d_in[4];
    const float* W1    = (const float*)d_in[5];
    const float* b1    = (const float*)d_in[6];
    const float* W2    = (const float*)d_in[7];
    const float* b2    = (const float*)d_in[8];
    float* out = (float*)d_out;

    cudaFuncSetAttribute(ode_kernel,
                         cudaFuncAttributeMaxDynamicSharedMemorySize, SMEM_BYTES);
    prep_kernel<<<41, 256>>>(graph, W1);
    ode_kernel<<<BB*CLX, TPB, SMEM_BYTES>>>(y0, Wg, a_src, a_dst, b1, W2, b2, out);
}